// round 2
// baseline (speedup 1.0000x reference)
#include <cuda_runtime.h>

#define NTOK 512
#define DSTATE 192
#define HID 512
#define EMB 1024
#define NEMB 32
#define KC 256
#define HSS 36   // smem row stride (floats): 144 B, 16B-aligned rows

// scratch (allocs forbidden -> device globals)
__device__ int g_start[NEMB + 1];
__device__ int g_tokens[NTOK];
__device__ float g_H[NTOK * 4 * HID]; // [slot][m][HID], grouped slot order

struct Params {
    const float* W1[4];
    const float* b1[4];
    const float* W2[4];
    const float* b2[4];
    const float* te[4];
};

// ---------------------------------------------------------------------------
// Kernel 0: group tokens by embodiment id. Handles int32 OR int64 id buffers.
// ---------------------------------------------------------------------------
__global__ void k_group(const int* __restrict__ ids_raw) {
    __shared__ int s_cnt[NEMB];
    __shared__ int s_pos[NEMB];
    __shared__ int s_i64;
    int tid = threadIdx.x; // 512 threads

    if (tid < NEMB) s_cnt[tid] = 0;
    if (tid == 0) s_i64 = 1;
    __syncthreads();

    // int64 ids (<32) have zero high words at all odd int32 indices.
    if (tid < 256) {
        if (ids_raw[2 * tid + 1] != 0) s_i64 = 0;
    }
    __syncthreads();

    int c = s_i64 ? ids_raw[2 * tid] : ids_raw[tid];
    atomicAdd(&s_cnt[c], 1);
    __syncthreads();

    if (tid <= NEMB) {
        int s = 0;
        for (int j = 0; j < tid && j < NEMB; j++) s += s_cnt[j];
        g_start[tid] = s;
        if (tid < NEMB) s_pos[tid] = s;
    }
    __syncthreads();

    int slot = atomicAdd(&s_pos[c], 1);
    g_tokens[slot] = tid;
}

// ---------------------------------------------------------------------------
// Kernel 1: H[slot][m][:] = relu(x_m . W1_m[e] + b1_m[e]) for grouped tokens.
// ---------------------------------------------------------------------------
__global__ void __launch_bounds__(512) k_stage1(const float* __restrict__ state, Params p) {
    const int Ls[4]   = {64, 64, 32, 32};
    const int offs[4] = {0, 64, 128, 160};
    int m = blockIdx.x & 3;
    int e = blockIdx.x >> 2;
    int L = Ls[m], off = offs[m];
    int s0 = g_start[e];
    int n  = g_start[e + 1] - s0;
    if (n == 0) return;

    int j = threadIdx.x;
    const float* __restrict__ W1 = p.W1[m] + (size_t)e * L * HID;
    float b = p.b1[m][e * HID + j];

    __shared__ float xs[16 * 64];

    for (int cb = 0; cb < n; cb += 16) {
        int rem = min(n - cb, 16);
        __syncthreads();
        for (int idx = j; idx < 16 * 64; idx += 512) {
            int tk = idx >> 6, l = idx & 63;
            float v = 0.f;
            if (tk < rem && l < L) {
                int tok = g_tokens[s0 + cb + tk];
                v = state[tok * DSTATE + off + l];
            }
            xs[idx] = v;
        }
        __syncthreads();

        float acc[16];
        #pragma unroll
        for (int t = 0; t < 16; t++) acc[t] = b;

        for (int l = 0; l < L; l++) {
            float w = W1[l * HID + j];
            #pragma unroll
            for (int t = 0; t < 16; t++)
                acc[t] = fmaf(xs[t * 64 + l], w, acc[t]);
        }

        #pragma unroll
        for (int t = 0; t < 16; t++) {
            if (t < rem)
                g_H[((size_t)(s0 + cb + t) * 4 + m) * HID + j] = fmaxf(acc[t], 0.f);
        }
    }
}

// ---------------------------------------------------------------------------
// Kernel 2: out = H . W2[e] + b2[e] + te.
// Block = (256-col tile, m, e); thread owns 2 adjacent columns.
// W2 slice streamed once (__ldcs, LDG.64); h via broadcast LDS.128;
// token pairs packed in f32x2 accumulators.
// ---------------------------------------------------------------------------
__device__ __forceinline__ void fma2(unsigned long long& acc,
                                     unsigned long long h2,
                                     unsigned long long w2) {
    asm("fma.rn.f32x2 %0, %1, %2, %0;" : "+l"(acc) : "l"(h2), "l"(w2));
}

template <int P>  // P even, 2..16: token pairs per chunk
__device__ __forceinline__ void run_chunk2(
    float* hs, const float* __restrict__ W2ec, const float* __restrict__ Hme,
    float2 init, int s0cb, int rem, int tid, int m, int c0,
    float* __restrict__ out)
{
    unsigned long long a0[P], a1[P];
    unsigned long long i0, i1;
    asm("mov.b64 %0, {%1,%1};" : "=l"(i0) : "r"(__float_as_uint(init.x)));
    asm("mov.b64 %0, {%1,%1};" : "=l"(i1) : "r"(__float_as_uint(init.y)));
    #pragma unroll
    for (int p = 0; p < P; p++) { a0[p] = i0; a1[p] = i1; }

    for (int kc = 0; kc < HID; kc += KC) {
        __syncthreads();
        // stage h transposed: hs[kk*HSS + tk], tk in [0, 2P)
        #pragma unroll
        for (int tk = 0; tk < 2 * P; tk++) {
            int slot = min(s0cb + tk, NTOK - 1); // clamp pad (discarded later)
            const float* src = Hme + (size_t)slot * (4 * HID) + kc;
            for (int kk = tid; kk < KC; kk += 128)
                hs[kk * HSS + tk] = src[kk];
        }
        __syncthreads();

        const float* wp = W2ec + (size_t)kc * EMB;
        #pragma unroll 2
        for (int kk = 0; kk < KC; kk++) {
            float2 w = __ldcs((const float2*)(wp + (size_t)kk * EMB));
            unsigned long long w0, w1;
            asm("mov.b64 %0, {%1,%1};" : "=l"(w0) : "r"(__float_as_uint(w.x)));
            asm("mov.b64 %0, {%1,%1};" : "=l"(w1) : "r"(__float_as_uint(w.y)));
            const float* hrow = hs + kk * HSS;
            #pragma unroll
            for (int p2 = 0; p2 < P / 2; p2++) {
                ulonglong2 hv = *(const ulonglong2*)(hrow + 4 * p2); // LDS.128 bcast
                fma2(a0[2 * p2],     hv.x, w0);
                fma2(a1[2 * p2],     hv.x, w1);
                fma2(a0[2 * p2 + 1], hv.y, w0);
                fma2(a1[2 * p2 + 1], hv.y, w1);
            }
        }
    }

    #pragma unroll
    for (int p = 0; p < P; p++) {
        float2 vA = *(float2*)&a0[p]; // col c0: (tok2p, tok2p+1)
        float2 vB = *(float2*)&a1[p]; // col c0+1
        int t0 = 2 * p;
        if (t0 < rem) {
            int tok = g_tokens[s0cb + t0];
            *(float2*)&out[((size_t)tok * 4 + m) * EMB + c0] = make_float2(vA.x, vB.x);
        }
        if (t0 + 1 < rem) {
            int tok = g_tokens[s0cb + t0 + 1];
            *(float2*)&out[((size_t)tok * 4 + m) * EMB + c0] = make_float2(vA.y, vB.y);
        }
    }
}

__global__ void __launch_bounds__(128) k_stage2(Params p, float* __restrict__ out) {
    int tile = blockIdx.x; // 0..3 (256 cols each)
    int m    = blockIdx.y; // 0..3
    int e    = blockIdx.z; // 0..31
    int s0 = g_start[e];
    int n  = g_start[e + 1] - s0;
    if (n == 0) return;

    int tid = threadIdx.x;
    int c0 = tile * 256 + tid * 2;
    const float* __restrict__ W2ec = p.W2[m] + (size_t)e * HID * EMB + c0;
    const float* __restrict__ Hme  = g_H + m * HID;
    float2 init = make_float2(p.b2[m][e * EMB + c0]     + p.te[m][c0],
                              p.b2[m][e * EMB + c0 + 1] + p.te[m][c0 + 1]);

    __shared__ __align__(16) float hs[KC * HSS];

    for (int cb = 0; cb < n; cb += 32) {
        int rem = min(n - cb, 32);
        int pairsEven = ((rem + 3) >> 2) << 1; // ceil(rem/2) rounded up to even
        int s0cb = s0 + cb;
        switch (pairsEven) {
#define CASE(PP) case PP: run_chunk2<PP>(hs, W2ec, Hme, init, s0cb, rem, tid, m, c0, out); break;
            CASE(2) CASE(4) CASE(6) CASE(8) CASE(10) CASE(12) CASE(14) CASE(16)
#undef CASE
        }
    }
}

// ---------------------------------------------------------------------------
extern "C" void kernel_launch(void* const* d_in, const int* in_sizes, int n_in,
                              void* d_out, int out_size) {
    const float* state = (const float*)d_in[0];
    const int*   ids   = (const int*)d_in[1];

    Params P;
    int base = 2;
    for (int m = 0; m < 4; m++) {
        P.W1[m] = (const float*)d_in[base + 0];
        P.b1[m] = (const float*)d_in[base + 1];
        P.W2[m] = (const float*)d_in[base + 2];
        P.b2[m] = (const float*)d_in[base + 3];
        P.te[m] = (const float*)d_in[base + 4];
        base += 5;
    }
    float* out = (float*)d_out;

    k_group<<<1, 512>>>(ids);
    k_stage1<<<128, 512>>>(state, P);
    k_stage2<<<dim3(4, 4, 32), 128>>>(P, out);
}

// round 3
// speedup vs baseline: 2.7898x; 2.7898x over previous
#include <cuda_runtime.h>

#define NTOK 512
#define DSTATE 192
#define HID 512
#define EMB 1024
#define NEMB 32
#define KC 256
#define HSS 36   // smem row stride (floats): 144 B rows, 16B-aligned

// scratch (allocs forbidden -> device globals)
__device__ int g_start[NEMB + 1];
__device__ int g_tokens[NTOK];
__device__ float g_H[NTOK * 4 * HID]; // [slot][m][HID], grouped slot order

struct Params {
    const float* W1[4];
    const float* b1[4];
    const float* W2[4];
    const float* b2[4];
    const float* te[4];
};

// ---------------------------------------------------------------------------
// Kernel 0: group tokens by embodiment id. Handles int32 OR int64 id buffers.
// ---------------------------------------------------------------------------
__global__ void k_group(const int* __restrict__ ids_raw) {
    __shared__ int s_cnt[NEMB];
    __shared__ int s_pos[NEMB];
    __shared__ int s_i64;
    int tid = threadIdx.x; // 512 threads

    if (tid < NEMB) s_cnt[tid] = 0;
    if (tid == 0) s_i64 = 1;
    __syncthreads();

    // int64 ids (<32) have zero high words at all odd int32 indices.
    if (tid < 256) {
        if (ids_raw[2 * tid + 1] != 0) s_i64 = 0;
    }
    __syncthreads();

    int c = s_i64 ? ids_raw[2 * tid] : ids_raw[tid];
    atomicAdd(&s_cnt[c], 1);
    __syncthreads();

    if (tid <= NEMB) {
        int s = 0;
        for (int j = 0; j < tid && j < NEMB; j++) s += s_cnt[j];
        g_start[tid] = s;
        if (tid < NEMB) s_pos[tid] = s;
    }
    __syncthreads();

    int slot = atomicAdd(&s_pos[c], 1);
    g_tokens[slot] = tid;
}

// ---------------------------------------------------------------------------
// Kernel 1: H[slot][m][:] = relu(x_m . W1_m[e] + b1_m[e]) for grouped tokens.
// ---------------------------------------------------------------------------
__global__ void __launch_bounds__(512) k_stage1(const float* __restrict__ state, Params p) {
    const int Ls[4]   = {64, 64, 32, 32};
    const int offs[4] = {0, 64, 128, 160};
    int m = blockIdx.x & 3;
    int e = blockIdx.x >> 2;
    int L = Ls[m], off = offs[m];
    int s0 = g_start[e];
    int n  = g_start[e + 1] - s0;
    if (n == 0) return;

    int j = threadIdx.x;
    const float* __restrict__ W1 = p.W1[m] + (size_t)e * L * HID;
    float b = p.b1[m][e * HID + j];

    __shared__ float xs[16 * 64];

    for (int cb = 0; cb < n; cb += 16) {
        int rem = min(n - cb, 16);
        __syncthreads();
        for (int idx = j; idx < 16 * 64; idx += 512) {
            int tk = idx >> 6, l = idx & 63;
            float v = 0.f;
            if (tk < rem && l < L) {
                int tok = g_tokens[s0 + cb + tk];
                v = state[tok * DSTATE + off + l];
            }
            xs[idx] = v;
        }
        __syncthreads();

        float acc[16];
        #pragma unroll
        for (int t = 0; t < 16; t++) acc[t] = b;

        for (int l = 0; l < L; l++) {
            float w = W1[l * HID + j];
            #pragma unroll
            for (int t = 0; t < 16; t++)
                acc[t] = fmaf(xs[t * 64 + l], w, acc[t]);
        }

        #pragma unroll
        for (int t = 0; t < 16; t++) {
            if (t < rem)
                g_H[((size_t)(s0 + cb + t) * 4 + m) * HID + j] = fmaxf(acc[t], 0.f);
        }
    }
}

// ---------------------------------------------------------------------------
// Kernel 2: out = H . W2[e] + b2[e] + te.
// Block = (128-col tile, m, e); thread owns 1 column.
// W2 streamed once via depth-D front-batched __ldcs groups (MLP = D lines/warp);
// h via broadcast LDS.128; token pairs packed in f32x2 accumulators.
// ---------------------------------------------------------------------------
__device__ __forceinline__ void fma2(unsigned long long& acc,
                                     unsigned long long h2,
                                     unsigned long long w2) {
    asm("fma.rn.f32x2 %0, %1, %2, %0;" : "+l"(acc) : "l"(h2), "l"(w2));
}

template <int P>  // P even, 2..16: token pairs in flight
__device__ __forceinline__ void run_chunk(
    float* hs, const float* __restrict__ W2ec, const float* __restrict__ Hme,
    float init, int s0cb, int rem, int tid, int m, int c,
    float* __restrict__ out)
{
    constexpr int D = (P <= 8) ? 16 : 8;  // prefetch depth (reg-pressure tradeoff)

    unsigned long long acc[P];
    unsigned long long ivl;
    asm("mov.b64 %0, {%1,%1};" : "=l"(ivl) : "r"(__float_as_uint(init)));
    #pragma unroll
    for (int p = 0; p < P; p++) acc[p] = ivl;

    for (int kc = 0; kc < HID; kc += KC) {
        __syncthreads();
        // stage h transposed: hs[kk*HSS + tk], tk in [0, 2P)
        #pragma unroll
        for (int tk = 0; tk < 2 * P; tk++) {
            int slot = min(s0cb + tk, NTOK - 1); // clamp pad (discarded later)
            const float* src = Hme + (size_t)slot * (4 * HID) + kc;
            #pragma unroll
            for (int kk = 0; kk < KC; kk += 128)
                hs[(kk + tid) * HSS + tk] = src[kk + tid];
        }
        __syncthreads();

        const float* wp = W2ec + (size_t)kc * EMB;
        #pragma unroll 1
        for (int g = 0; g < KC; g += D) {
            // front-batch D independent streaming loads -> D lines in flight
            float w[D];
            #pragma unroll
            for (int j = 0; j < D; j++)
                w[j] = __ldcs(wp + (size_t)(g + j) * EMB);

            #pragma unroll
            for (int j = 0; j < D; j++) {
                unsigned long long w2;
                asm("mov.b64 %0, {%1,%1};" : "=l"(w2) : "r"(__float_as_uint(w[j])));
                const float* hrow = hs + (g + j) * HSS;
                #pragma unroll
                for (int p2 = 0; p2 < P / 2; p2++) {
                    ulonglong2 hv = *(const ulonglong2*)(hrow + 4 * p2); // LDS.128 bcast
                    fma2(acc[2 * p2],     hv.x, w2);
                    fma2(acc[2 * p2 + 1], hv.y, w2);
                }
            }
        }
    }

    #pragma unroll
    for (int p = 0; p < P; p++) {
        float2 v = *(float2*)&acc[p];
        int t0 = 2 * p;
        if (t0 < rem) {
            int tok = g_tokens[s0cb + t0];
            out[((size_t)tok * 4 + m) * EMB + c] = v.x;
        }
        if (t0 + 1 < rem) {
            int tok = g_tokens[s0cb + t0 + 1];
            out[((size_t)tok * 4 + m) * EMB + c] = v.y;
        }
    }
}

__global__ void __launch_bounds__(128) k_stage2(Params p, float* __restrict__ out) {
    int tile = blockIdx.x; // 0..7 (128 cols each)
    int m    = blockIdx.y; // 0..3
    int e    = blockIdx.z; // 0..31
    int s0 = g_start[e];
    int n  = g_start[e + 1] - s0;
    if (n == 0) return;

    int tid = threadIdx.x;
    int c = tile * 128 + tid;
    const float* __restrict__ W2ec = p.W2[m] + (size_t)e * HID * EMB + c;
    const float* __restrict__ Hme  = g_H + m * HID;
    float init = p.b2[m][e * EMB + c] + p.te[m][c];

    __shared__ __align__(16) float hs[KC * HSS];

    for (int cb = 0; cb < n; cb += 32) {
        int rem = min(n - cb, 32);
        int pairsEven = ((rem + 3) >> 2) << 1; // ceil(rem/2) rounded up to even
        int s0cb = s0 + cb;
        switch (pairsEven) {
#define CASE(PP) case PP: run_chunk<PP>(hs, W2ec, Hme, init, s0cb, rem, tid, m, c, out); break;
            CASE(2) CASE(4) CASE(6) CASE(8) CASE(10) CASE(12) CASE(14) CASE(16)
#undef CASE
        }
    }
}

// ---------------------------------------------------------------------------
extern "C" void kernel_launch(void* const* d_in, const int* in_sizes, int n_in,
                              void* d_out, int out_size) {
    const float* state = (const float*)d_in[0];
    const int*   ids   = (const int*)d_in[1];

    Params P;
    int base = 2;
    for (int m = 0; m < 4; m++) {
        P.W1[m] = (const float*)d_in[base + 0];
        P.b1[m] = (const float*)d_in[base + 1];
        P.W2[m] = (const float*)d_in[base + 2];
        P.b2[m] = (const float*)d_in[base + 3];
        P.te[m] = (const float*)d_in[base + 4];
        base += 5;
    }
    float* out = (float*)d_out;

    k_group<<<1, 512>>>(ids);
    k_stage1<<<128, 512>>>(state, P);
    k_stage2<<<dim3(8, 4, 32), 128>>>(P, out);
}